// round 6
// baseline (speedup 1.0000x reference)
#include <cuda_runtime.h>
#include <cuda_bf16.h>
#include <cstdint>

// ---------------------------------------------------------------------------
// AxialAttention (K=56, G=8, CIN=512, COUT=512) — fp32 with packed f32x2 FMA
//   k1: qkv GEMM [50176 x 512] x [512 x 1024], fma.rn.f32x2 microkernel
//       (FFMA2 on B300 = 2x fp32 FMA throughput), BN fold, writes Q/K/V
//       transposed to [b][w][row][c]
//   k2: per-(b,w,g) logits
//   k3: in-place softmax over w (faithful axis=-2)
//   k4: per-(b,w,g) sv/sve + BN fold -> out [b][i][w][512]
// ---------------------------------------------------------------------------

#define EPS 1e-3f
typedef unsigned long long ull;

__device__ float g_Q[12845056];   // [16][56 w][56 i][256]
__device__ float g_K[12845056];
__device__ float g_V[25690112];   // [16][56 w][56 j][512]
__device__ float g_L[22478848];   // [16][56 w][8 g][3136 ij]

__device__ __forceinline__ float dot4(float4 a, float4 b) {
    return a.x*b.x + a.y*b.y + a.z*b.z + a.w*b.w;
}
__device__ __forceinline__ void fma2(ull& d, ull a, ull b) {
    asm("fma.rn.f32x2 %0, %1, %2, %0;" : "+l"(d) : "l"(a), "l"(b));
}
__device__ __forceinline__ ull dup2(float a) {
    ull d;
    asm("mov.b64 %0, {%1, %1};" : "=l"(d) : "r"(__float_as_uint(a)));
    return d;
}
__device__ __forceinline__ float2 unpack2(ull v) {
    unsigned lo, hi;
    asm("mov.b64 {%0, %1}, %2;" : "=r"(lo), "=r"(hi) : "l"(v));
    float2 f; f.x = __uint_as_float(lo); f.y = __uint_as_float(hi); return f;
}

// ---------------------------------------------------------------------------
// k1: QKV GEMM, BM=128 BN=128 BK=16, 256 thr, 8x8 microtile (f32x2 over j),
//     double-buffered. smem: As2 (A duplicated as {a,a} 64-bit) + Bs.
//     As2 stage: [16 k][130 ull] = 16640 B (x2), Bs stage: [16 k][132 f] = 8448 B (x2)
// ---------------------------------------------------------------------------
#define AS2_STAGE 16640
#define BS_BASE   33280
#define BS_STAGE  8448
#define SMEM_GEMM 50176

__global__ __launch_bounds__(256, 2) void qkv_gemm_kernel(
    const float* __restrict__ x,
    const float* __restrict__ Wq, const float* __restrict__ Wk, const float* __restrict__ Wv,
    const float* __restrict__ pq, const float* __restrict__ pk, const float* __restrict__ pv)
{
    extern __shared__ char smem[];

    const int tid = threadIdx.x;
    const int n0  = blockIdx.x * 128;   // 0..1023
    const int m0  = blockIdx.y * 128;   // 0..50048

    const float* W; const float* P; float* dst; int ncols, colbase;
    if (n0 < 256)      { W = Wq; P = pq; dst = g_Q; ncols = 256; colbase = n0;       }
    else if (n0 < 512) { W = Wk; P = pk; dst = g_K; ncols = 256; colbase = n0 - 256; }
    else               { W = Wv; P = pv; dst = g_V; ncols = 512; colbase = n0 - 512; }

    const int ra = tid >> 2;          // 0..63
    const int ca = (tid & 3) << 2;    // 0,4,8,12
    const int kb = tid >> 4;          // 0..15
    const int nb = (tid & 15) << 3;   // 0..120
    const int ty = tid >> 4;          // 0..15
    const int tx = tid & 15;          // 0..15

    ull acc[8][4];
    #pragma unroll
    for (int a = 0; a < 8; a++)
        #pragma unroll
        for (int c = 0; c < 4; c++) acc[a][c] = 0ULL;

    // prologue: tile 0
    {
        float4 a0 = *(const float4*)(x + (size_t)(m0 + ra) * 512 + ca);
        float4 a1 = *(const float4*)(x + (size_t)(m0 + 64 + ra) * 512 + ca);
        float4 b0 = *(const float4*)(W + kb * ncols + colbase + nb);
        float4 b1 = *(const float4*)(W + kb * ncols + colbase + nb + 4);
        ull*   A2 = (ull*)smem;                       // stage 0
        float* Bs = (float*)(smem + BS_BASE);
        A2[(ca+0)*130 + ra]    = dup2(a0.x); A2[(ca+1)*130 + ra]    = dup2(a0.y);
        A2[(ca+2)*130 + ra]    = dup2(a0.z); A2[(ca+3)*130 + ra]    = dup2(a0.w);
        A2[(ca+0)*130 + 64+ra] = dup2(a1.x); A2[(ca+1)*130 + 64+ra] = dup2(a1.y);
        A2[(ca+2)*130 + 64+ra] = dup2(a1.z); A2[(ca+3)*130 + 64+ra] = dup2(a1.w);
        *(float4*)(Bs + kb*132 + nb)     = b0;
        *(float4*)(Bs + kb*132 + nb + 4) = b1;
    }
    __syncthreads();

    for (int ks = 0; ks < 32; ks++) {
        const int cur = ks & 1;
        float4 a0, a1, b0, b1;
        if (ks < 31) {
            const int k0 = (ks + 1) * 16;
            a0 = *(const float4*)(x + (size_t)(m0 + ra) * 512 + k0 + ca);
            a1 = *(const float4*)(x + (size_t)(m0 + 64 + ra) * 512 + k0 + ca);
            b0 = *(const float4*)(W + (k0 + kb) * ncols + colbase + nb);
            b1 = *(const float4*)(W + (k0 + kb) * ncols + colbase + nb + 4);
        }
        {
            const char* Abase = smem + cur * AS2_STAGE;
            const char* Bbase = smem + BS_BASE + cur * BS_STAGE;
            #pragma unroll
            for (int kk = 0; kk < 16; kk++) {
                ull ad[8], bd[4];
                const ulonglong2* ap = (const ulonglong2*)(Abase + kk*1040 + ty*64);
                ulonglong2 t;
                t = ap[0]; ad[0] = t.x; ad[1] = t.y;
                t = ap[1]; ad[2] = t.x; ad[3] = t.y;
                t = ap[2]; ad[4] = t.x; ad[5] = t.y;
                t = ap[3]; ad[6] = t.x; ad[7] = t.y;
                const ulonglong2* bp = (const ulonglong2*)(Bbase + kk*528 + tx*32);
                t = bp[0]; bd[0] = t.x; bd[1] = t.y;
                t = bp[1]; bd[2] = t.x; bd[3] = t.y;
                #pragma unroll
                for (int i2 = 0; i2 < 8; i2++)
                    #pragma unroll
                    for (int j2 = 0; j2 < 4; j2++)
                        fma2(acc[i2][j2], ad[i2], bd[j2]);
            }
        }
        if (ks < 31) {
            const int nxt = cur ^ 1;
            ull*   A2 = (ull*)(smem + nxt * AS2_STAGE);
            float* Bs = (float*)(smem + BS_BASE + nxt * BS_STAGE);
            A2[(ca+0)*130 + ra]    = dup2(a0.x); A2[(ca+1)*130 + ra]    = dup2(a0.y);
            A2[(ca+2)*130 + ra]    = dup2(a0.z); A2[(ca+3)*130 + ra]    = dup2(a0.w);
            A2[(ca+0)*130 + 64+ra] = dup2(a1.x); A2[(ca+1)*130 + 64+ra] = dup2(a1.y);
            A2[(ca+2)*130 + 64+ra] = dup2(a1.z); A2[(ca+3)*130 + 64+ra] = dup2(a1.w);
            *(float4*)(Bs + kb*132 + nb)     = b0;
            *(float4*)(Bs + kb*132 + nb + 4) = b1;
        }
        __syncthreads();
    }

    // epilogue: fold BN, write transposed [b][w][row][c]
    float sc[8], sh[8];
    #pragma unroll
    for (int c = 0; c < 8; c++) {
        const int ch = colbase + tx*8 + c;
        const float s = P[ch] * rsqrtf(P[3*ncols + ch] + EPS);
        sc[c] = s;
        sh[c] = P[ncols + ch] - P[2*ncols + ch] * s;
    }
    #pragma unroll
    for (int r = 0; r < 8; r++) {
        const int m   = m0 + ty*8 + r;
        const int b   = m / 3136;
        const int rem = m - b*3136;
        const int i   = rem / 56;
        const int w   = rem - i*56;
        float* drow = dst + (size_t)((b*56 + w)*56 + i) * ncols + colbase + tx*8;
        float v[8];
        #pragma unroll
        for (int jp = 0; jp < 4; jp++) {
            float2 f = unpack2(acc[r][jp]);
            v[2*jp] = f.x; v[2*jp+1] = f.y;
        }
        float4 o0, o1;
        o0.x = fmaf(v[0], sc[0], sh[0]); o0.y = fmaf(v[1], sc[1], sh[1]);
        o0.z = fmaf(v[2], sc[2], sh[2]); o0.w = fmaf(v[3], sc[3], sh[3]);
        o1.x = fmaf(v[4], sc[4], sh[4]); o1.y = fmaf(v[5], sc[5], sh[5]);
        o1.z = fmaf(v[6], sc[6], sh[6]); o1.w = fmaf(v[7], sc[7], sh[7]);
        *(float4*)drow     = o0;
        *(float4*)(drow+4) = o1;
    }
}

// ---------------------------------------------------------------------------
// k2: logits per (b,w,g)
// ---------------------------------------------------------------------------
__global__ __launch_bounds__(256) void logits_kernel(
    const float* __restrict__ q_rel, const float* __restrict__ k_rel,
    const float* __restrict__ pqk, const float* __restrict__ pqr, const float* __restrict__ pkr)
{
    __shared__ float qg_s[56][36];
    __shared__ float kg_s[56][36];
    __shared__ float qrel_s[111][36];
    __shared__ float krel_s[111][36];

    const int tid = threadIdx.x;
    const int bw  = blockIdx.x;
    const int g   = blockIdx.y;

    for (int idx = tid; idx < 111*32; idx += 256) {
        const int d = idx >> 5, c = idx & 31;
        qrel_s[d][c] = q_rel[idx];
        krel_s[d][c] = k_rel[idx];
    }
    const float* qbase = g_Q + bw * 56 * 256;
    const float* kbase = g_K + bw * 56 * 256;
    for (int idx = tid; idx < 56*32; idx += 256) {
        const int i = idx >> 5, c = idx & 31;
        qg_s[i][c] = qbase[i*256 + g*32 + c];
        kg_s[i][c] = kbase[i*256 + g*32 + c];
    }
    __syncthreads();

    if (tid >= 196) return;
    const int ti = tid / 14, tj = tid % 14;
    const int i0 = ti*4, j0 = tj*4;
    const int dq0 = 55 + i0 - j0;
    const int dk0 = 55 + j0 - i0;

    const float sqk = pqk[g] * rsqrtf(pqk[24+g] + EPS);
    const float sqr = pqr[g] * rsqrtf(pqr[24+g] + EPS);
    const float skr = pkr[g] * rsqrtf(pkr[24+g] + EPS);
    const float tsum = (pqk[8+g] - pqk[16+g]*sqk)
                     + (pqr[8+g] - pqr[16+g]*sqr)
                     + (pkr[8+g] - pkr[16+g]*skr);

    float aqk[4][4], aqr[4][4], akr[4][4];
    #pragma unroll
    for (int a = 0; a < 4; a++)
        #pragma unroll
        for (int b2 = 0; b2 < 4; b2++) { aqk[a][b2]=0.f; aqr[a][b2]=0.f; akr[a][b2]=0.f; }

    #pragma unroll
    for (int c4 = 0; c4 < 32; c4 += 4) {
        float4 qa[4], kb[4];
        #pragma unroll
        for (int a = 0; a < 4; a++) {
            qa[a] = *(const float4*)&qg_s[i0+a][c4];
            kb[a] = *(const float4*)&kg_s[j0+a][c4];
        }
        #pragma unroll
        for (int a = 0; a < 4; a++)
            #pragma unroll
            for (int b2 = 0; b2 < 4; b2++)
                aqk[a][b2] += dot4(qa[a], kb[b2]);
        {
            float4 r7[7];
            #pragma unroll
            for (int t = 0; t < 7; t++) r7[t] = *(const float4*)&qrel_s[dq0-3+t][c4];
            #pragma unroll
            for (int a = 0; a < 4; a++)
                #pragma unroll
                for (int b2 = 0; b2 < 4; b2++)
                    aqr[a][b2] += dot4(qa[a], r7[3 + a - b2]);
        }
        {
            float4 r7[7];
            #pragma unroll
            for (int t = 0; t < 7; t++) r7[t] = *(const float4*)&krel_s[dk0-3+t][c4];
            #pragma unroll
            for (int a = 0; a < 4; a++)
                #pragma unroll
                for (int b2 = 0; b2 < 4; b2++)
                    akr[a][b2] += dot4(kb[b2], r7[3 + b2 - a]);
        }
    }

    float* Lp = g_L + ((size_t)bw*8 + g)*3136;
    #pragma unroll
    for (int a = 0; a < 4; a++) {
        float4 o;
        o.x = sqk*aqk[a][0] + sqr*aqr[a][0] + skr*akr[a][0] + tsum;
        o.y = sqk*aqk[a][1] + sqr*aqr[a][1] + skr*akr[a][1] + tsum;
        o.z = sqk*aqk[a][2] + sqr*aqr[a][2] + skr*akr[a][2] + tsum;
        o.w = sqk*aqk[a][3] + sqr*aqr[a][3] + skr*akr[a][3] + tsum;
        *(float4*)&Lp[(i0+a)*56 + j0] = o;
    }
}

// ---------------------------------------------------------------------------
// k3: softmax over w (axis=-2), in place
// ---------------------------------------------------------------------------
__global__ __launch_bounds__(64) void softmax_kernel()
{
    const int t  = threadIdx.x;
    const int ij = blockIdx.x * 64 + t;
    const int g  = blockIdx.y;
    const int b  = blockIdx.z;
    float* base = g_L + ((size_t)b*448 + g)*3136 + ij;
    const int ws = 8*3136;

    float v[56];
    float mx = -3.4e38f;
    #pragma unroll
    for (int w = 0; w < 56; w++) { v[w] = base[w*ws]; mx = fmaxf(mx, v[w]); }
    float s = 0.f;
    #pragma unroll
    for (int w = 0; w < 56; w++) { v[w] = __expf(v[w] - mx); s += v[w]; }
    const float inv = 1.f / s;
    #pragma unroll
    for (int w = 0; w < 56; w++) base[w*ws] = v[w] * inv;
}

// ---------------------------------------------------------------------------
// k4: attention output per (b,w,g)
// ---------------------------------------------------------------------------
__global__ __launch_bounds__(256) void attn_out_kernel(
    const float* __restrict__ v_rel,
    const float* __restrict__ psv, const float* __restrict__ psve,
    float* __restrict__ out)
{
    extern __shared__ float sm[];
    float* Vg     = sm;              // [56][64]
    float* vrel_s = sm + 3584;       // [111][64]
    float* sim_s  = sm + 10688;      // [56][56]

    const int tid = threadIdx.x;
    const int bw  = blockIdx.x;
    const int g   = blockIdx.y;
    const int b   = bw / 56, w = bw - b*56;

    const float* vsrc = g_V + (size_t)bw * (56*512) + g*64;
    for (int idx = tid; idx < 3584; idx += 256) {
        const int j = idx >> 6, c = idx & 63;
        Vg[idx] = vsrc[j*512 + c];
    }
    for (int idx = tid; idx < 7104; idx += 256) vrel_s[idx] = v_rel[idx];
    const float* simsrc = g_L + ((size_t)bw*8 + g)*3136;
    for (int idx = tid; idx < 3136; idx += 256) sim_s[idx] = simsrc[idx];
    __syncthreads();

    if (tid >= 224) return;
    const int ti = tid >> 4, tc = tid & 15;
    const int i0 = ti*4, c0 = tc*4;
    const int ch0 = g*64 + c0;

    float asv[4][4], asve[4][4];
    #pragma unroll
    for (int a = 0; a < 4; a++)
        #pragma unroll
        for (int c = 0; c < 4; c++) { asv[a][c]=0.f; asve[a][c]=0.f; }

    #pragma unroll 4
    for (int j = 0; j < 56; j++) {
        const float4 vv = *(const float4*)&Vg[j*64 + c0];
        #pragma unroll
        for (int a = 0; a < 4; a++) {
            const float s = sim_s[(i0+a)*56 + j];
            asv[a][0] = fmaf(s, vv.x, asv[a][0]);
            asv[a][1] = fmaf(s, vv.y, asv[a][1]);
            asv[a][2] = fmaf(s, vv.z, asv[a][2]);
            asv[a][3] = fmaf(s, vv.w, asv[a][3]);
        }
    }
    for (int d = 52 - i0; d <= 110 - i0; d++) {
        const float4 vr = *(const float4*)&vrel_s[d*64 + c0];
        #pragma unroll
        for (int a = 0; a < 4; a++) {
            const int j = i0 + a + d - 55;
            if ((unsigned)j < 56u) {
                const float s = sim_s[(i0+a)*56 + j];
                asve[a][0] = fmaf(s, vr.x, asve[a][0]);
                asve[a][1] = fmaf(s, vr.y, asve[a][1]);
                asve[a][2] = fmaf(s, vr.z, asve[a][2]);
                asve[a][3] = fmaf(s, vr.w, asve[a][3]);
            }
        }
    }

    float s1[4], t1[4], s2[4], t2[4];
    #pragma unroll
    for (int cc = 0; cc < 4; cc++) {
        const int ch = ch0 + cc;
        const float a1 = psv[ch] * rsqrtf(psv[1536+ch] + EPS);
        s1[cc] = a1; t1[cc] = psv[512+ch] - psv[1024+ch]*a1;
        const float a2 = psve[ch] * rsqrtf(psve[1536+ch] + EPS);
        s2[cc] = a2; t2[cc] = psve[512+ch] - psve[1024+ch]*a2;
    }
    #pragma unroll
    for (int a = 0; a < 4; a++) {
        float4 o;
        o.x = asv[a][0]*s1[0] + t1[0] + asve[a][0]*s2[0] + t2[0];
        o.y = asv[a][1]*s1[1] + t1[1] + asve[a][1]*s2[1] + t2[1];
        o.z = asv[a][2]*s1[2] + t1[2] + asve[a][2]*s2[2] + t2[2];
        o.w = asv[a][3]*s1[3] + t1[3] + asve[a][3]*s2[3] + t2[3];
        *(float4*)&out[(((b*56 + i0 + a)*56 + w) * 512) + ch0] = o;
    }
}

// ---------------------------------------------------------------------------
extern "C" void kernel_launch(void* const* d_in, const int* in_sizes, int n_in,
                              void* d_out, int out_size)
{
    const float* x     = (const float*)d_in[0];
    const float* Wq    = (const float*)d_in[1];
    const float* Wk    = (const float*)d_in[2];
    const float* Wv    = (const float*)d_in[3];
    const float* q_rel = (const float*)d_in[4];
    const float* k_rel = (const float*)d_in[5];
    const float* v_rel = (const float*)d_in[6];
    const float* p_q   = (const float*)d_in[7];
    const float* p_k   = (const float*)d_in[8];
    const float* p_v   = (const float*)d_in[9];
    const float* p_qk  = (const float*)d_in[10];
    const float* p_qr  = (const float*)d_in[11];
    const float* p_kr  = (const float*)d_in[12];
    const float* p_sv  = (const float*)d_in[13];
    const float* p_sve = (const float*)d_in[14];
    float* out = (float*)d_out;

    const int smem_k4 = (3584 + 7104 + 3136) * 4;  // 55296 B
    cudaFuncSetAttribute(qkv_gemm_kernel,
                         cudaFuncAttributeMaxDynamicSharedMemorySize, SMEM_GEMM);
    cudaFuncSetAttribute(attn_out_kernel,
                         cudaFuncAttributeMaxDynamicSharedMemorySize, smem_k4);

    qkv_gemm_kernel<<<dim3(8, 392), 256, SMEM_GEMM>>>(x, Wq, Wk, Wv, p_q, p_k, p_v);
    logits_kernel<<<dim3(896, 8), 256>>>(q_rel, k_rel, p_qk, p_qr, p_kr);
    softmax_kernel<<<dim3(49, 8, 16), 64>>>();
    attn_out_kernel<<<dim3(896, 8), 256, smem_k4>>>(v_rel, p_sv, p_sve, out);
}

// round 7
// speedup vs baseline: 1.5927x; 1.5927x over previous
#include <cuda_runtime.h>
#include <cuda_bf16.h>
#include <cstdint>

// ---------------------------------------------------------------------------
// AxialAttention (K=56, G=8, CIN=512, COUT=512)
//   k0a: split x (fp32) -> bf16 hi/lo pair arrays
//   k0b: transpose+split W -> g_whi/g_wlo [1024 n][512 k] bf16
//   k1 : qkv GEMM via mma.sync m16n8k16 bf16 (3-product split = ~fp32 accuracy),
//        BN fold, writes Q/K/V transposed to [b][w][row][c] fp32
//   k2 : per-(b,w,g) logits      k3: in-place softmax over w
//   k4 : per-(b,w,g) sv/sve + BN fold -> out [b][i][w][512]
// ---------------------------------------------------------------------------

#define EPS 1e-3f

__device__ float g_Q[12845056];   // [16][56 w][56 i][256]
__device__ float g_K[12845056];
__device__ float g_V[25690112];   // [16][56 w][56 j][512]
__device__ float g_L[22478848];   // [16][56 w][8 g][3136 ij]
__device__ __align__(16) __nv_bfloat16 g_xhi[25690112];  // [50176 m][512 k]
__device__ __align__(16) __nv_bfloat16 g_xlo[25690112];
__device__ __align__(16) __nv_bfloat16 g_whi[524288];    // [1024 n][512 k]
__device__ __align__(16) __nv_bfloat16 g_wlo[524288];

__device__ __forceinline__ float dot4(float4 a, float4 b) {
    return a.x*b.x + a.y*b.y + a.z*b.z + a.w*b.w;
}
__device__ __forceinline__ uint32_t smem_u32(const void* p) {
    uint32_t a;
    asm("{ .reg .u64 t; cvta.to.shared.u64 t, %1; cvt.u32.u64 %0, t; }" : "=r"(a) : "l"(p));
    return a;
}
__device__ __forceinline__ void ldsm4(unsigned* r, uint32_t a) {
    asm volatile("ldmatrix.sync.aligned.m8n8.x4.shared.b16 {%0,%1,%2,%3}, [%4];"
        : "=r"(r[0]), "=r"(r[1]), "=r"(r[2]), "=r"(r[3]) : "r"(a));
}
__device__ __forceinline__ void mma16816(float* d, const unsigned* a, const unsigned* b) {
    asm volatile("mma.sync.aligned.m16n8k16.row.col.f32.bf16.bf16.f32 "
        "{%0,%1,%2,%3}, {%4,%5,%6,%7}, {%8,%9}, {%0,%1,%2,%3};"
        : "+f"(d[0]), "+f"(d[1]), "+f"(d[2]), "+f"(d[3])
        : "r"(a[0]), "r"(a[1]), "r"(a[2]), "r"(a[3]), "r"(b[0]), "r"(b[1]));
}
// smem swizzle: rows of 32 bf16 (64B = 4 chunks of 16B)
__device__ __forceinline__ uint32_t swz(int row, int chunk) {
    return (uint32_t)(row * 64 + ((chunk ^ (row & 3) ^ ((row >> 2) & 1)) << 4));
}
__device__ __forceinline__ void split_pair(float a, float b, unsigned& hi2, unsigned& lo2) {
    __nv_bfloat162 h = __floats2bfloat162_rn(a, b);
    float ra = a - __bfloat162float(h.x);
    float rb = b - __bfloat162float(h.y);
    __nv_bfloat162 l = __floats2bfloat162_rn(ra, rb);
    hi2 = *(unsigned*)&h;
    lo2 = *(unsigned*)&l;
}

// ---------------------------------------------------------------------------
// k0a: split x -> g_xhi/g_xlo. one float4 per thread.
// ---------------------------------------------------------------------------
__global__ __launch_bounds__(256) void split_x_kernel(const float* __restrict__ x)
{
    const int idx = blockIdx.x * 256 + threadIdx.x;   // 6422528 float4s
    float4 v = ((const float4*)x)[idx];
    uint2 h, l;
    split_pair(v.x, v.y, h.x, l.x);
    split_pair(v.z, v.w, h.y, l.y);
    ((uint2*)g_xhi)[idx] = h;
    ((uint2*)g_xlo)[idx] = l;
}

// ---------------------------------------------------------------------------
// k0b: transpose + split W -> g_whi/g_wlo [n][k]
// ---------------------------------------------------------------------------
__global__ __launch_bounds__(256) void split_w_kernel(
    const float* __restrict__ Wq, const float* __restrict__ Wk, const float* __restrict__ Wv)
{
    __shared__ float t[32][33];
    const int n0 = blockIdx.x * 32, k0 = blockIdx.y * 32;
    const float* W; int ncols, col0;
    if (n0 < 256)      { W = Wq; ncols = 256; col0 = n0;       }
    else if (n0 < 512) { W = Wk; ncols = 256; col0 = n0 - 256; }
    else               { W = Wv; ncols = 512; col0 = n0 - 512; }
    const int tx = threadIdx.x & 31, ty = threadIdx.x >> 5;
    #pragma unroll
    for (int i = 0; i < 32; i += 8)
        t[ty + i][tx] = W[(k0 + ty + i) * ncols + col0 + tx];
    __syncthreads();
    #pragma unroll
    for (int i = 0; i < 32; i += 8) {
        const float v = t[tx][ty + i];
        const __nv_bfloat16 h = __float2bfloat16_rn(v);
        g_whi[(n0 + ty + i) * 512 + k0 + tx] = h;
        g_wlo[(n0 + ty + i) * 512 + k0 + tx] = __float2bfloat16_rn(v - __bfloat162float(h));
    }
}

// ---------------------------------------------------------------------------
// k1: mma.sync bf16 QKV GEMM. BM=128 BN=128 BK=32, 256 thr (8 warps, 4Mx2N),
//     double-buffered swizzled smem: stage = {Ahi,Alo,Bhi,Blo} x 8KB = 32KB.
// ---------------------------------------------------------------------------
#define STG 32768
#define SMEM_MMA (2*STG + 1024)

__global__ __launch_bounds__(256, 1) void qkv_mma_kernel(
    const float* __restrict__ pq, const float* __restrict__ pk, const float* __restrict__ pv)
{
    extern __shared__ char smem[];
    float* Ssc = (float*)(smem + 2*STG);
    float* Tsc = Ssc + 128;

    const int tid  = threadIdx.x;
    const int lane = tid & 31, wid = tid >> 5;
    const int mbase = (wid >> 1) * 32;     // 4 M-warps
    const int nbase = (wid & 1) * 64;      // 2 N-warps
    const int n0 = blockIdx.x * 128;
    const int m0 = blockIdx.y * 128;
    const uint32_t sb = smem_u32(smem);

    const float* P; float* dst; int ncols, colbase;
    if (n0 < 256)      { P = pq; dst = g_Q; ncols = 256; colbase = n0;       }
    else if (n0 < 512) { P = pk; dst = g_K; ncols = 256; colbase = n0 - 256; }
    else               { P = pv; dst = g_V; ncols = 512; colbase = n0 - 512; }

    if (tid < 128) {
        const int ch = colbase + tid;
        const float s = P[ch] * rsqrtf(P[3*ncols + ch] + EPS);
        Ssc[tid] = s;
        Tsc[tid] = P[ncols + ch] - P[2*ncols + ch] * s;
    }

    // producer mapping: thread -> (row = tid/2, chunk pair = (tid&1)*2)
    const int prow = tid >> 1;
    const int pc   = (tid & 1) * 2;
    const size_t aoff = (size_t)(m0 + prow) * 512;
    const size_t boff = (size_t)(n0 + prow) * 512;
    const uint32_t so0 = swz(prow, pc), so1 = swz(prow, pc + 1);

    float acc[2][8][4];
    #pragma unroll
    for (int mt = 0; mt < 2; mt++)
        #pragma unroll
        for (int nt = 0; nt < 8; nt++)
            #pragma unroll
            for (int c = 0; c < 4; c++) acc[mt][nt][c] = 0.f;

    // prologue: stage 0
    {
        const int koff = pc * 8;
        const uint4* pa = (const uint4*)(g_xhi + aoff + koff);
        const uint4* pb = (const uint4*)(g_xlo + aoff + koff);
        const uint4* pcu = (const uint4*)(g_whi + boff + koff);
        const uint4* pd = (const uint4*)(g_wlo + boff + koff);
        char* s = smem;
        *(uint4*)(s + so0)          = pa[0]; *(uint4*)(s + so1)          = pa[1];
        *(uint4*)(s + 8192  + so0)  = pb[0]; *(uint4*)(s + 8192  + so1)  = pb[1];
        *(uint4*)(s + 16384 + so0)  = pcu[0]; *(uint4*)(s + 16384 + so1) = pcu[1];
        *(uint4*)(s + 24576 + so0)  = pd[0]; *(uint4*)(s + 24576 + so1)  = pd[1];
    }
    __syncthreads();

    for (int ks = 0; ks < 16; ks++) {
        const int cur = ks & 1;
        uint4 pf[8];
        if (ks < 15) {
            const int koff = (ks + 1) * 32 + pc * 8;
            const uint4* pa = (const uint4*)(g_xhi + aoff + koff);
            const uint4* pb = (const uint4*)(g_xlo + aoff + koff);
            const uint4* pcu = (const uint4*)(g_whi + boff + koff);
            const uint4* pd = (const uint4*)(g_wlo + boff + koff);
            pf[0] = pa[0]; pf[1] = pa[1];
            pf[2] = pb[0]; pf[3] = pb[1];
            pf[4] = pcu[0]; pf[5] = pcu[1];
            pf[6] = pd[0]; pf[7] = pd[1];
        }
        const uint32_t stb = sb + cur * STG;
        #pragma unroll
        for (int kst = 0; kst < 2; kst++) {
            unsigned ah[2][4], al[2][4], bh[16], bl[16];
            #pragma unroll
            for (int mt = 0; mt < 2; mt++) {
                const int row = mbase + mt*16 + (lane & 15);
                const int ch  = kst*2 + (lane >> 4);
                const uint32_t ad = stb + swz(row, ch);
                ldsm4(ah[mt], ad);
                ldsm4(al[mt], ad + 8192);
            }
            #pragma unroll
            for (int p = 0; p < 4; p++) {
                const int row = nbase + (2*p + (lane >> 4)) * 8 + (lane & 7);
                const int ch  = kst*2 + ((lane >> 3) & 1);
                const uint32_t bd = stb + 16384 + swz(row, ch);
                ldsm4(&bh[p*4], bd);
                ldsm4(&bl[p*4], bd + 8192);
            }
            #pragma unroll
            for (int mt = 0; mt < 2; mt++)
                #pragma unroll
                for (int nt = 0; nt < 8; nt++) {
                    mma16816(acc[mt][nt], ah[mt], &bh[nt*2]);
                    mma16816(acc[mt][nt], al[mt], &bh[nt*2]);
                    mma16816(acc[mt][nt], ah[mt], &bl[nt*2]);
                }
        }
        __syncthreads();
        if (ks < 15) {
            char* s = smem + (cur ^ 1) * STG;
            *(uint4*)(s + so0)         = pf[0]; *(uint4*)(s + so1)         = pf[1];
            *(uint4*)(s + 8192  + so0) = pf[2]; *(uint4*)(s + 8192  + so1) = pf[3];
            *(uint4*)(s + 16384 + so0) = pf[4]; *(uint4*)(s + 16384 + so1) = pf[5];
            *(uint4*)(s + 24576 + so0) = pf[6]; *(uint4*)(s + 24576 + so1) = pf[7];
            __syncthreads();
        }
    }

    // epilogue: BN fold, transposed store [b][w][row][c]
    #pragma unroll
    for (int mt = 0; mt < 2; mt++) {
        #pragma unroll
        for (int half = 0; half < 2; half++) {
            const int m = m0 + mbase + mt*16 + (lane >> 2) + half*8;
            const int b = m / 3136;
            const int rem = m - b*3136;
            const int i = rem / 56;
            const int w = rem - i*56;
            float* dr = dst + (size_t)((b*56 + w)*56 + i) * ncols + colbase;
            #pragma unroll
            for (int nt = 0; nt < 8; nt++) {
                const int col = nbase + nt*8 + (lane & 3)*2;
                float2 o;
                o.x = acc[mt][nt][half*2+0] * Ssc[col]   + Tsc[col];
                o.y = acc[mt][nt][half*2+1] * Ssc[col+1] + Tsc[col+1];
                *(float2*)(dr + col) = o;
            }
        }
    }
}

// ---------------------------------------------------------------------------
// k2: logits per (b,w,g)
// ---------------------------------------------------------------------------
__global__ __launch_bounds__(256) void logits_kernel(
    const float* __restrict__ q_rel, const float* __restrict__ k_rel,
    const float* __restrict__ pqk, const float* __restrict__ pqr, const float* __restrict__ pkr)
{
    __shared__ float qg_s[56][36];
    __shared__ float kg_s[56][36];
    __shared__ float qrel_s[111][36];
    __shared__ float krel_s[111][36];

    const int tid = threadIdx.x;
    const int bw  = blockIdx.x;
    const int g   = blockIdx.y;

    for (int idx = tid; idx < 111*32; idx += 256) {
        const int d = idx >> 5, c = idx & 31;
        qrel_s[d][c] = q_rel[idx];
        krel_s[d][c] = k_rel[idx];
    }
    const float* qbase = g_Q + bw * 56 * 256;
    const float* kbase = g_K + bw * 56 * 256;
    for (int idx = tid; idx < 56*32; idx += 256) {
        const int i = idx >> 5, c = idx & 31;
        qg_s[i][c] = qbase[i*256 + g*32 + c];
        kg_s[i][c] = kbase[i*256 + g*32 + c];
    }
    __syncthreads();

    if (tid >= 196) return;
    const int ti = tid / 14, tj = tid % 14;
    const int i0 = ti*4, j0 = tj*4;
    const int dq0 = 55 + i0 - j0;
    const int dk0 = 55 + j0 - i0;

    const float sqk = pqk[g] * rsqrtf(pqk[24+g] + EPS);
    const float sqr = pqr[g] * rsqrtf(pqr[24+g] + EPS);
    const float skr = pkr[g] * rsqrtf(pkr[24+g] + EPS);
    const float tsum = (pqk[8+g] - pqk[16+g]*sqk)
                     + (pqr[8+g] - pqr[16+g]*sqr)
                     + (pkr[8+g] - pkr[16+g]*skr);

    float aqk[4][4], aqr[4][4], akr[4][4];
    #pragma unroll
    for (int a = 0; a < 4; a++)
        #pragma unroll
        for (int b2 = 0; b2 < 4; b2++) { aqk[a][b2]=0.f; aqr[a][b2]=0.f; akr[a][b2]=0.f; }

    #pragma unroll
    for (int c4 = 0; c4 < 32; c4 += 4) {
        float4 qa[4], kb[4];
        #pragma unroll
        for (int a = 0; a < 4; a++) {
            qa[a] = *(const float4*)&qg_s[i0+a][c4];
            kb[a] = *(const float4*)&kg_s[j0+a][c4];
        }
        #pragma unroll
        for (int a = 0; a < 4; a++)
            #pragma unroll
            for (int b2 = 0; b2 < 4; b2++)
                aqk[a][b2] += dot4(qa[a], kb[b2]);
        {
            float4 r7[7];
            #pragma unroll
            for (int t = 0; t < 7; t++) r7[t] = *(const float4*)&qrel_s[dq0-3+t][c4];
            #pragma unroll
            for (int a = 0; a < 4; a++)
                #pragma unroll
                for (int b2 = 0; b2 < 4; b2++)
                    aqr[a][b2] += dot4(qa[a], r7[3 + a - b2]);
        }
        {
            float4 r7[7];
            #pragma unroll
            for (int t = 0; t < 7; t++) r7[t] = *(const float4*)&krel_s[dk0-3+t][c4];
            #pragma unroll
            for (int a = 0; a < 4; a++)
                #pragma unroll
                for (int b2 = 0; b2 < 4; b2++)
                    akr[a][b2] += dot4(kb[b2], r7[3 + b2 - a]);
        }
    }

    float* Lp = g_L + ((size_t)bw*8 + g)*3136;
    #pragma unroll
    for (int a = 0; a < 4; a++) {
        float4 o;
        o.x = sqk*aqk[a][0] + sqr*aqr[a][0] + skr*akr[a][0] + tsum;
        o.y = sqk*aqk[a][1] + sqr*aqr[a][1] + skr*akr[a][1] + tsum;
        o.z = sqk*aqk[a][2] + sqr*aqr[a][2] + skr*akr[a][2] + tsum;
        o.w = sqk*aqk[a][3] + sqr*aqr[a][3] + skr*akr[a][3] + tsum;
        *(float4*)&Lp[(i0+a)*56 + j0] = o;
    }
}

// ---------------------------------------------------------------------------
// k3: softmax over w (axis=-2), in place
// ---------------------------------------------------------------------------
__global__ __launch_bounds__(64) void softmax_kernel()
{
    const int t  = threadIdx.x;
    const int ij = blockIdx.x * 64 + t;
    const int g  = blockIdx.y;
    const int b  = blockIdx.z;
    float* base = g_L + ((size_t)b*448 + g)*3136 + ij;
    const int ws = 8*3136;

    float v[56];
    float mx = -3.4e38f;
    #pragma unroll
    for (int w = 0; w < 56; w++) { v[w] = base[w*ws]; mx = fmaxf(mx, v[w]); }
    float s = 0.f;
    #pragma unroll
    for (int w = 0; w < 56; w++) { v[w] = __expf(v[w] - mx); s += v[w]; }
    const float inv = 1.f / s;
    #pragma unroll
    for (int w = 0; w < 56; w++) base[w*ws] = v[w] * inv;
}

// ---------------------------------------------------------------------------
// k4: attention output per (b,w,g)
// ---------------------------------------------------------------------------
__global__ __launch_bounds__(256) void attn_out_kernel(
    const float* __restrict__ v_rel,
    const float* __restrict__ psv, const float* __restrict__ psve,
    float* __restrict__ out)
{
    extern __shared__ float sm[];
    float* Vg     = sm;              // [56][64]
    float* vrel_s = sm + 3584;       // [111][64]
    float* sim_s  = sm + 10688;      // [56][56]

    const int tid = threadIdx.x;
    const int bw  = blockIdx.x;
    const int g   = blockIdx.y;
    const int b   = bw / 56, w = bw - b*56;

    const float* vsrc = g_V + (size_t)bw * (56*512) + g*64;
    for (int idx = tid; idx < 3584; idx += 256) {
        const int j = idx >> 6, c = idx & 63;
        Vg[idx] = vsrc[j*512 + c];
    }
    for (int idx = tid; idx < 7104; idx += 256) vrel_s[idx] = v_rel[idx];
    const float* simsrc = g_L + ((size_t)bw*8 + g)*3136;
    for (int idx = tid; idx < 3136; idx += 256) sim_s[idx] = simsrc[idx];
    __syncthreads();

    if (tid >= 224) return;
    const int ti = tid >> 4, tc = tid & 15;
    const int i0 = ti*4, c0 = tc*4;
    const int ch0 = g*64 + c0;

    float asv[4][4], asve[4][4];
    #pragma unroll
    for (int a = 0; a < 4; a++)
        #pragma unroll
        for (int c = 0; c < 4; c++) { asv[a][c]=0.f; asve[a][c]=0.f; }

    #pragma unroll 4
    for (int j = 0; j < 56; j++) {
        const float4 vv = *(const float4*)&Vg[j*64 + c0];
        #pragma unroll
        for (int a = 0; a < 4; a++) {
            const float s = sim_s[(i0+a)*56 + j];
            asv[a][0] = fmaf(s, vv.x, asv[a][0]);
            asv[a][1] = fmaf(s, vv.y, asv[a][1]);
            asv[a][2] = fmaf(s, vv.z, asv[a][2]);
            asv[a][3] = fmaf(s, vv.w, asv[a][3]);
        }
    }
    for (int d = 52 - i0; d <= 110 - i0; d++) {
        const float4 vr = *(const float4*)&vrel_s[d*64 + c0];
        #pragma unroll
        for (int a = 0; a < 4; a++) {
            const int j = i0 + a + d - 55;
            if ((unsigned)j < 56u) {
                const float s = sim_s[(i0+a)*56 + j];
                asve[a][0] = fmaf(s, vr.x, asve[a][0]);
                asve[a][1] = fmaf(s, vr.y, asve[a][1]);
                asve[a][2] = fmaf(s, vr.z, asve[a][2]);
                asve[a][3] = fmaf(s, vr.w, asve[a][3]);
            }
        }
    }

    float s1[4], t1[4], s2[4], t2[4];
    #pragma unroll
    for (int cc = 0; cc < 4; cc++) {
        const int ch = ch0 + cc;
        const float a1 = psv[ch] * rsqrtf(psv[1536+ch] + EPS);
        s1[cc] = a1; t1[cc] = psv[512+ch] - psv[1024+ch]*a1;
        const float a2 = psve[ch] * rsqrtf(psve[1536+ch] + EPS);
        s2[cc] = a2; t2[cc] = psve[512+ch] - psve[1024+ch]*a2;
    }
    #pragma unroll
    for (int a = 0; a < 4; a++) {
        float4 o;
        o.x = asv[a][0]*s1[0] + t1[0] + asve[a][0]*s2[0] + t2[0];
        o.y = asv[a][1]*s1[1] + t1[1] + asve[a][1]*s2[1] + t2[1];
        o.z = asv[a][2]*s1[2] + t1[2] + asve[a][2]*s2[2] + t2[2];
        o.w = asv[a][3]*s1[3] + t1[3] + asve[a][3]*s2[3] + t2[3];
        *(float4*)&out[(((b*56 + i0 + a)*56 + w) * 512) + ch0] = o;
    }
}

// ---------------------------------------------------------------------------
extern "C" void kernel_launch(void* const* d_in, const int* in_sizes, int n_in,
                              void* d_out, int out_size)
{
    const float* x     = (const float*)d_in[0];
    const float* Wq    = (const float*)d_in[1];
    const float* Wk    = (const float*)d_in[2];
    const float* Wv    = (const float*)d_in[3];
    const float* q_rel = (const float*)d_in[4];
    const float* k_rel = (const float*)d_in[5];
    const float* v_rel = (const float*)d_in[6];
    const float* p_q   = (const float*)d_in[7];
    const float* p_k   = (const float*)d_in[8];
    const float* p_v   = (const float*)d_in[9];
    const float* p_qk  = (const float*)d_in[10];
    const float* p_qr  = (const float*)d_in[11];
    const float* p_kr  = (const float*)d_in[12];
    const float* p_sv  = (const float*)d_in[13];
    const float* p_sve = (const float*)d_in[14];
    float* out = (float*)d_out;

    const int smem_k4 = (3584 + 7104 + 3136) * 4;  // 55296 B
    cudaFuncSetAttribute(qkv_mma_kernel,
                         cudaFuncAttributeMaxDynamicSharedMemorySize, SMEM_MMA);
    cudaFuncSetAttribute(attn_out_kernel,
                         cudaFuncAttributeMaxDynamicSharedMemorySize, smem_k4);

    split_x_kernel<<<25088, 256>>>(x);
    split_w_kernel<<<dim3(32, 16), 256>>>(Wq, Wk, Wv);
    qkv_mma_kernel<<<dim3(8, 392), 256, SMEM_MMA>>>(p_q, p_k, p_v);
    logits_kernel<<<dim3(896, 8), 256>>>(q_rel, k_rel, p_qk, p_qr, p_kr);
    softmax_kernel<<<dim3(49, 8, 16), 64>>>();
    attn_out_kernel<<<dim3(896, 8), 256, smem_k4>>>(v_rel, p_sv, p_sve, out);
}

// round 9
// speedup vs baseline: 2.1324x; 1.3388x over previous
#include <cuda_runtime.h>
#include <cuda_bf16.h>
#include <cstdint>

// ---------------------------------------------------------------------------
// AxialAttention (K=56, G=8, CIN=512, COUT=512)
//   k0 : transpose+split W -> g_whi/g_wlo [1024 n][512 k] bf16
//   k1 : qkv GEMM via mma.sync m16n8k16 bf16 (3-product split), inline x split,
//        BN fold, writes Q/K/V transposed to [b][w][row][c] fp32
//   k2 : logits via mma.sync: QK^T + diag-gather of Q*qrel^T and K*krel^T
//   k3 : in-place softmax over w
//   k4 : per-(b,w,g) sv/sve + BN fold -> out [b][i][w][512]
// ---------------------------------------------------------------------------

#define EPS 1e-3f

__device__ float g_Q[12845056];   // [16][56 w][56 i][256]
__device__ float g_K[12845056];
__device__ float g_V[25690112];   // [16][56 w][56 j][512]
__device__ float g_L[22478848];   // [16][56 w][8 g][3136 ij]
__device__ __align__(16) __nv_bfloat16 g_whi[524288];    // [1024 n][512 k]
__device__ __align__(16) __nv_bfloat16 g_wlo[524288];

__device__ __forceinline__ uint32_t smem_u32(const void* p) {
    uint32_t a;
    asm("{ .reg .u64 t; cvta.to.shared.u64 t, %1; cvt.u32.u64 %0, t; }" : "=r"(a) : "l"(p));
    return a;
}
__device__ __forceinline__ void ldsm4(unsigned* r, uint32_t a) {
    asm volatile("ldmatrix.sync.aligned.m8n8.x4.shared.b16 {%0,%1,%2,%3}, [%4];"
        : "=r"(r[0]), "=r"(r[1]), "=r"(r[2]), "=r"(r[3]) : "r"(a));
}
__device__ __forceinline__ void mma16816(float* d, const unsigned* a, const unsigned* b) {
    asm volatile("mma.sync.aligned.m16n8k16.row.col.f32.bf16.bf16.f32 "
        "{%0,%1,%2,%3}, {%4,%5,%6,%7}, {%8,%9}, {%0,%1,%2,%3};"
        : "+f"(d[0]), "+f"(d[1]), "+f"(d[2]), "+f"(d[3])
        : "r"(a[0]), "r"(a[1]), "r"(a[2]), "r"(a[3]), "r"(b[0]), "r"(b[1]));
}
// smem swizzle: rows of 32 bf16 (64B = 4 chunks of 16B)
__device__ __forceinline__ uint32_t swz(int row, int chunk) {
    return (uint32_t)(row * 64 + ((chunk ^ (row & 3) ^ ((row >> 2) & 1)) << 4));
}
__device__ __forceinline__ void split_pair(float a, float b, unsigned& hi2, unsigned& lo2) {
    __nv_bfloat162 h = __floats2bfloat162_rn(a, b);
    float ra = a - __bfloat162float(h.x);
    float rb = b - __bfloat162float(h.y);
    __nv_bfloat162 l = __floats2bfloat162_rn(ra, rb);
    hi2 = *(unsigned*)&h;
    lo2 = *(unsigned*)&l;
}
__device__ __forceinline__ void split8(float4 a, float4 b, uint4& hi, uint4& lo) {
    split_pair(a.x, a.y, hi.x, lo.x);
    split_pair(a.z, a.w, hi.y, lo.y);
    split_pair(b.x, b.y, hi.z, lo.z);
    split_pair(b.z, b.w, hi.w, lo.w);
}

// ---------------------------------------------------------------------------
// k0: transpose + split W -> g_whi/g_wlo [n][k]
// ---------------------------------------------------------------------------
__global__ __launch_bounds__(256) void split_w_kernel(
    const float* __restrict__ Wq, const float* __restrict__ Wk, const float* __restrict__ Wv)
{
    __shared__ float t[32][33];
    const int n0 = blockIdx.x * 32, k0 = blockIdx.y * 32;
    const float* W; int ncols, col0;
    if (n0 < 256)      { W = Wq; ncols = 256; col0 = n0;       }
    else if (n0 < 512) { W = Wk; ncols = 256; col0 = n0 - 256; }
    else               { W = Wv; ncols = 512; col0 = n0 - 512; }
    const int tx = threadIdx.x & 31, ty = threadIdx.x >> 5;
    #pragma unroll
    for (int i = 0; i < 32; i += 8)
        t[ty + i][tx] = W[(k0 + ty + i) * ncols + col0 + tx];
    __syncthreads();
    #pragma unroll
    for (int i = 0; i < 32; i += 8) {
        const float v = t[tx][ty + i];
        const __nv_bfloat16 h = __float2bfloat16_rn(v);
        g_whi[(n0 + ty + i) * 512 + k0 + tx] = h;
        g_wlo[(n0 + ty + i) * 512 + k0 + tx] = __float2bfloat16_rn(v - __bfloat162float(h));
    }
}

// ---------------------------------------------------------------------------
// k1: mma.sync bf16 QKV GEMM. BM=128 BN=128 BK=32, 256 thr (8 warps, 4Mx2N),
//     double-buffered swizzled smem, inline fp32->bf16 hi/lo split of x.
// ---------------------------------------------------------------------------
#define STG 32768
#define SMEM_MMA (2*STG + 1024)

__global__ __launch_bounds__(256, 1) void qkv_mma_kernel(
    const float* __restrict__ x,
    const float* __restrict__ pq, const float* __restrict__ pk, const float* __restrict__ pv)
{
    extern __shared__ char smem[];
    float* Ssc = (float*)(smem + 2*STG);
    float* Tsc = Ssc + 128;

    const int tid  = threadIdx.x;
    const int lane = tid & 31, wid = tid >> 5;
    const int mbase = (wid >> 1) * 32;
    const int nbase = (wid & 1) * 64;
    const int n0 = blockIdx.x * 128;
    const int m0 = blockIdx.y * 128;
    const uint32_t sb = smem_u32(smem);

    const float* P; float* dst; int ncols, colbase;
    if (n0 < 256)      { P = pq; dst = g_Q; ncols = 256; colbase = n0;       }
    else if (n0 < 512) { P = pk; dst = g_K; ncols = 256; colbase = n0 - 256; }
    else               { P = pv; dst = g_V; ncols = 512; colbase = n0 - 512; }

    if (tid < 128) {
        const int ch = colbase + tid;
        const float s = P[ch] * rsqrtf(P[3*ncols + ch] + EPS);
        Ssc[tid] = s;
        Tsc[tid] = P[ncols + ch] - P[2*ncols + ch] * s;
    }

    const int prow = tid >> 1;
    const int pc   = (tid & 1) * 2;
    const size_t aoff = (size_t)(m0 + prow) * 512;
    const size_t boff = (size_t)(n0 + prow) * 512;
    const uint32_t so0 = swz(prow, pc), so1 = swz(prow, pc + 1);

    float acc[2][8][4];
    #pragma unroll
    for (int mt = 0; mt < 2; mt++)
        #pragma unroll
        for (int nt = 0; nt < 8; nt++)
            #pragma unroll
            for (int c = 0; c < 4; c++) acc[mt][nt][c] = 0.f;

    // prologue: stage 0
    {
        const int koff = pc * 8;
        const float4* px = (const float4*)(x + aoff + koff);
        float4 x0 = px[0], x1 = px[1], x2 = px[2], x3 = px[3];
        uint4 h0, l0, h1, l1;
        split8(x0, x1, h0, l0);
        split8(x2, x3, h1, l1);
        const uint4* pwh = (const uint4*)(g_whi + boff + koff);
        const uint4* pwl = (const uint4*)(g_wlo + boff + koff);
        char* s = smem;
        *(uint4*)(s + so0)          = h0; *(uint4*)(s + so1)          = h1;
        *(uint4*)(s + 8192  + so0)  = l0; *(uint4*)(s + 8192  + so1)  = l1;
        *(uint4*)(s + 16384 + so0)  = pwh[0]; *(uint4*)(s + 16384 + so1) = pwh[1];
        *(uint4*)(s + 24576 + so0)  = pwl[0]; *(uint4*)(s + 24576 + so1) = pwl[1];
    }
    __syncthreads();

    for (int ks = 0; ks < 16; ks++) {
        const int cur = ks & 1;
        float4 fx[4]; uint4 fw[4];
        if (ks < 15) {
            const int koff = (ks + 1) * 32 + pc * 8;
            const float4* px = (const float4*)(x + aoff + koff);
            fx[0] = px[0]; fx[1] = px[1]; fx[2] = px[2]; fx[3] = px[3];
            const uint4* pwh = (const uint4*)(g_whi + boff + koff);
            const uint4* pwl = (const uint4*)(g_wlo + boff + koff);
            fw[0] = pwh[0]; fw[1] = pwh[1];
            fw[2] = pwl[0]; fw[3] = pwl[1];
        }
        const uint32_t stb = sb + cur * STG;
        #pragma unroll
        for (int kst = 0; kst < 2; kst++) {
            unsigned ah[2][4], al[2][4], bh[16], bl[16];
            #pragma unroll
            for (int mt = 0; mt < 2; mt++) {
                const int row = mbase + mt*16 + (lane & 15);
                const int ch  = kst*2 + (lane >> 4);
                const uint32_t ad = stb + swz(row, ch);
                ldsm4(ah[mt], ad);
                ldsm4(al[mt], ad + 8192);
            }
            #pragma unroll
            for (int p = 0; p < 4; p++) {
                const int row = nbase + (2*p + (lane >> 4)) * 8 + (lane & 7);
                const int ch  = kst*2 + ((lane >> 3) & 1);
                const uint32_t bd = stb + 16384 + swz(row, ch);
                ldsm4(&bh[p*4], bd);
                ldsm4(&bl[p*4], bd + 8192);
            }
            #pragma unroll
            for (int mt = 0; mt < 2; mt++)
                #pragma unroll
                for (int nt = 0; nt < 8; nt++) {
                    mma16816(acc[mt][nt], ah[mt], &bh[nt*2]);
                    mma16816(acc[mt][nt], al[mt], &bh[nt*2]);
                    mma16816(acc[mt][nt], ah[mt], &bl[nt*2]);
                }
        }
        __syncthreads();
        if (ks < 15) {
            uint4 h0, l0, h1, l1;
            split8(fx[0], fx[1], h0, l0);
            split8(fx[2], fx[3], h1, l1);
            char* s = smem + (cur ^ 1) * STG;
            *(uint4*)(s + so0)         = h0;    *(uint4*)(s + so1)         = h1;
            *(uint4*)(s + 8192  + so0) = l0;    *(uint4*)(s + 8192  + so1) = l1;
            *(uint4*)(s + 16384 + so0) = fw[0]; *(uint4*)(s + 16384 + so1) = fw[1];
            *(uint4*)(s + 24576 + so0) = fw[2]; *(uint4*)(s + 24576 + so1) = fw[3];
            __syncthreads();
        }
    }

    // epilogue: BN fold, transposed store [b][w][row][c]
    #pragma unroll
    for (int mt = 0; mt < 2; mt++) {
        #pragma unroll
        for (int half = 0; half < 2; half++) {
            const int m = m0 + mbase + mt*16 + (lane >> 2) + half*8;
            const int b = m / 3136;
            const int rem = m - b*3136;
            const int i = rem / 56;
            const int w = rem - i*56;
            float* dr = dst + (size_t)((b*56 + w)*56 + i) * ncols + colbase;
            #pragma unroll
            for (int nt = 0; nt < 8; nt++) {
                const int col = nbase + nt*8 + (lane & 3)*2;
                float2 o;
                o.x = acc[mt][nt][half*2+0] * Ssc[col]   + Tsc[col];
                o.y = acc[mt][nt][half*2+1] * Ssc[col+1] + Tsc[col+1];
                *(float2*)(dr + col) = o;
            }
        }
    }
}

// ---------------------------------------------------------------------------
// k2: logits via mma.sync. One block per (b,w,g), 128 threads (4 warps).
//   Qr_full = Q*qrel^T [56,112], Kr_full = K*krel^T [56,112] -> smem
//   QK = Q*K^T [56,56] -> regs; combine with diagonal gathers + BN fold.
// ---------------------------------------------------------------------------
#define OFF_QHI  0
#define OFF_QLO  4096
#define OFF_KHI  8192
#define OFF_KLO  12288
#define OFF_RQHI 16384
#define OFF_RQLO 23552
#define OFF_RKHI 30720
#define OFF_RKLO 37888
#define OFF_QRS  45056
#define OFF_KRS  74240
#define SMEM_LOGITS 103424

__global__ __launch_bounds__(128) void logits_mma_kernel(
    const float* __restrict__ q_rel, const float* __restrict__ k_rel,
    const float* __restrict__ pqk, const float* __restrict__ pqr, const float* __restrict__ pkr)
{
    extern __shared__ char sm[];
    const uint32_t sb = smem_u32(sm);
    const int tid = threadIdx.x;
    const int lane = tid & 31, wid = tid >> 5;
    const int bw = blockIdx.x;
    const int g  = blockIdx.y;

    // --- convert Q, K group slices (56 rows x 32 ch) to bf16 hi/lo, swizzled
    const float* qbase = g_Q + (size_t)bw * 56 * 256 + g * 32;
    const float* kbase = g_K + (size_t)bw * 56 * 256 + g * 32;
    for (int t = tid; t < 224; t += 128) {
        const int row = t >> 2, ch = t & 3;
        const uint32_t o = swz(row, ch);
        float4 a = *(const float4*)(qbase + row*256 + ch*8);
        float4 b = *(const float4*)(qbase + row*256 + ch*8 + 4);
        uint4 hi, lo; split8(a, b, hi, lo);
        *(uint4*)(sm + OFF_QHI + o) = hi;
        *(uint4*)(sm + OFF_QLO + o) = lo;
        a = *(const float4*)(kbase + row*256 + ch*8);
        b = *(const float4*)(kbase + row*256 + ch*8 + 4);
        split8(a, b, hi, lo);
        *(uint4*)(sm + OFF_KHI + o) = hi;
        *(uint4*)(sm + OFF_KLO + o) = lo;
    }
    // --- convert rel tables (111 rows x 32)
    for (int t = tid; t < 444; t += 128) {
        const int row = t >> 2, ch = t & 3;
        const uint32_t o = swz(row, ch);
        float4 a = *(const float4*)(q_rel + row*32 + ch*8);
        float4 b = *(const float4*)(q_rel + row*32 + ch*8 + 4);
        uint4 hi, lo; split8(a, b, hi, lo);
        *(uint4*)(sm + OFF_RQHI + o) = hi;
        *(uint4*)(sm + OFF_RQLO + o) = lo;
        a = *(const float4*)(k_rel + row*32 + ch*8);
        b = *(const float4*)(k_rel + row*32 + ch*8 + 4);
        split8(a, b, hi, lo);
        *(uint4*)(sm + OFF_RKHI + o) = hi;
        *(uint4*)(sm + OFF_RKLO + o) = lo;
    }
    __syncthreads();

    const float sqk = pqk[g] * rsqrtf(pqk[24+g] + EPS);
    const float sqr = pqr[g] * rsqrtf(pqr[24+g] + EPS);
    const float skr = pkr[g] * rsqrtf(pkr[24+g] + EPS);
    const float tsum = (pqk[8+g] - pqk[16+g]*sqk)
                     + (pqr[8+g] - pqr[16+g]*sqr)
                     + (pkr[8+g] - pkr[16+g]*skr);

    const int mrow0 = wid * 16;
    float* qrs = (float*)(sm + OFF_QRS);
    float* krs = (float*)(sm + OFF_KRS);
    const int fr = lane >> 2, fc = (lane & 3) * 2;

    // --- Qr_full = Q * qrel^T
    {
        unsigned ah[2][4], al[2][4];
        #pragma unroll
        for (int kst = 0; kst < 2; kst++) {
            const int row = mrow0 + (lane & 15);
            const int ch  = kst*2 + (lane >> 4);
            ldsm4(ah[kst], sb + OFF_QHI + swz(row, ch));
            ldsm4(al[kst], sb + OFF_QLO + swz(row, ch));
        }
        float acc[14][4];
        #pragma unroll
        for (int nt = 0; nt < 14; nt++)
            #pragma unroll
            for (int c = 0; c < 4; c++) acc[nt][c] = 0.f;
        #pragma unroll
        for (int kst = 0; kst < 2; kst++)
            #pragma unroll
            for (int p = 0; p < 7; p++) {
                unsigned bh[4], bl[4];
                const int brow = (2*p + (lane >> 4)) * 8 + (lane & 7);
                const int bch  = kst*2 + ((lane >> 3) & 1);
                ldsm4(bh, sb + OFF_RQHI + swz(brow, bch));
                ldsm4(bl, sb + OFF_RQLO + swz(brow, bch));
                #pragma unroll
                for (int t2 = 0; t2 < 2; t2++) {
                    mma16816(acc[2*p+t2], ah[kst], &bh[2*t2]);
                    mma16816(acc[2*p+t2], al[kst], &bh[2*t2]);
                    mma16816(acc[2*p+t2], ah[kst], &bl[2*t2]);
                }
            }
        #pragma unroll
        for (int nt = 0; nt < 14; nt++) {
            *(float2*)&qrs[(mrow0+fr)*114   + nt*8 + fc] = make_float2(acc[nt][0], acc[nt][1]);
            *(float2*)&qrs[(mrow0+fr+8)*114 + nt*8 + fc] = make_float2(acc[nt][2], acc[nt][3]);
        }
    }
    // --- Kr_full = K * krel^T
    {
        unsigned ah[2][4], al[2][4];
        #pragma unroll
        for (int kst = 0; kst < 2; kst++) {
            const int row = mrow0 + (lane & 15);
            const int ch  = kst*2 + (lane >> 4);
            ldsm4(ah[kst], sb + OFF_KHI + swz(row, ch));
            ldsm4(al[kst], sb + OFF_KLO + swz(row, ch));
        }
        float acc[14][4];
        #pragma unroll
        for (int nt = 0; nt < 14; nt++)
            #pragma unroll
            for (int c = 0; c < 4; c++) acc[nt][c] = 0.f;
        #pragma unroll
        for (int kst = 0; kst < 2; kst++)
            #pragma unroll
            for (int p = 0; p < 7; p++) {
                unsigned bh[4], bl[4];
                const int brow = (2*p + (lane >> 4)) * 8 + (lane & 7);
                const int bch  = kst*2 + ((lane >> 3) & 1);
                ldsm4(bh, sb + OFF_RKHI + swz(brow, bch));
                ldsm4(bl, sb + OFF_RKLO + swz(brow, bch));
                #pragma unroll
                for (int t2 = 0; t2 < 2; t2++) {
                    mma16816(acc[2*p+t2], ah[kst], &bh[2*t2]);
                    mma16816(acc[2*p+t2], al[kst], &bh[2*t2]);
                    mma16816(acc[2*p+t2], ah[kst], &bl[2*t2]);
                }
            }
        #pragma unroll
        for (int nt = 0; nt < 14; nt++) {
            *(float2*)&krs[(mrow0+fr)*114   + nt*8 + fc] = make_float2(acc[nt][0], acc[nt][1]);
            *(float2*)&krs[(mrow0+fr+8)*114 + nt*8 + fc] = make_float2(acc[nt][2], acc[nt][3]);
        }
    }
    // --- QK = Q * K^T  (8 n-tiles; tile 7 covers padded K rows 56-63, discarded)
    float qk[8][4];
    #pragma unroll
    for (int nt = 0; nt < 8; nt++)
        #pragma unroll
        for (int c = 0; c < 4; c++) qk[nt][c] = 0.f;
    {
        unsigned ah[2][4], al[2][4];
        #pragma unroll
        for (int kst = 0; kst < 2; kst++) {
            const int row = mrow0 + (lane & 15);
            const int ch  = kst*2 + (lane >> 4);
            ldsm4(ah[kst], sb + OFF_QHI + swz(row, ch));
            ldsm4(al[kst], sb + OFF_QLO + swz(row, ch));
        }
        #pragma unroll
        for (int kst = 0; kst < 2; kst++)
            #pragma unroll
            for (int p = 0; p < 4; p++) {
                unsigned bh[4], bl[4];
                const int brow = (2*p + (lane >> 4)) * 8 + (lane & 7);
                const int bch  = kst*2 + ((lane >> 3) & 1);
                ldsm4(bh, sb + OFF_KHI + swz(brow, bch));
                ldsm4(bl, sb + OFF_KLO + swz(brow, bch));
                #pragma unroll
                for (int t2 = 0; t2 < 2; t2++) {
                    mma16816(qk[2*p+t2], ah[kst], &bh[2*t2]);
                    mma16816(qk[2*p+t2], al[kst], &bh[2*t2]);
                    mma16816(qk[2*p+t2], ah[kst], &bl[2*t2]);
                }
            }
    }
    __syncthreads();

    // --- combine with diagonal gathers, write logits
    float* Lp = g_L + ((size_t)bw*8 + g)*3136;
    #pragma unroll
    for (int nt = 0; nt < 7; nt++) {
        const int j0 = nt*8 + fc;
        #pragma unroll
        for (int half = 0; half < 2; half++) {
            const int i = mrow0 + fr + half*8;
            if (i < 56) {
                const int dq = 55 + i - j0;
                float2 o;
                o.x = sqk*qk[nt][half*2+0] + sqr*qrs[i*114 + dq]
                    + skr*krs[j0*114 + 55 + j0 - i] + tsum;
                o.y = sqk*qk[nt][half*2+1] + sqr*qrs[i*114 + dq - 1]
                    + skr*krs[(j0+1)*114 + 56 + j0 - i] + tsum;
                *(float2*)&Lp[i*56 + j0] = o;
            }
        }
    }
}

// ---------------------------------------------------------------------------
// k3: softmax over w (axis=-2), in place
// ---------------------------------------------------------------------------
__global__ __launch_bounds__(64) void softmax_kernel()
{
    const int t  = threadIdx.x;
    const int ij = blockIdx.x * 64 + t;
    const int g  = blockIdx.y;
    const int b  = blockIdx.z;
    float* base = g_L + ((size_t)b*448 + g)*3136 + ij;
    const int ws = 8*3136;

    float v[56];
    float mx = -3.4e38f;
    #pragma unroll
    for (int w = 0; w < 56; w++) { v[w] = base[w*ws]; mx = fmaxf(mx, v[w]); }
    float s = 0.f;
    #pragma unroll
    for (int w = 0; w < 56; w++) { v[w] = __expf(v[w] - mx); s += v[w]; }
    const float inv = 1.f / s;
    #pragma unroll
    for (int w = 0; w < 56; w++) base[w*ws] = v[w] * inv;
}

// ---------------------------------------------------------------------------
// k4: attention output per (b,w,g)
// ---------------------------------------------------------------------------
__global__ __launch_bounds__(256) void attn_out_kernel(
    const float* __restrict__ v_rel,
    const float* __restrict__ psv, const float* __restrict__ psve,
    float* __restrict__ out)
{
    extern __shared__ float smf[];
    float* Vg     = smf;              // [56][64]
    float* vrel_s = smf + 3584;       // [111][64]
    float* sim_s  = smf + 10688;      // [56][56]

    const int tid = threadIdx.x;
    const int bw  = blockIdx.x;
    const int g   = blockIdx.y;
    const int b   = bw / 56, w = bw - b*56;

    const float* vsrc = g_V + (size_t)bw * (56*512) + g*64;
    for (int idx = tid; idx < 3584; idx += 256) {
        const int j = idx >> 6, c = idx & 63;
        Vg[idx] = vsrc[j*512 + c];
    }
    for (int idx = tid; idx < 7104; idx += 256) vrel_s[idx] = v_rel[idx];
    const float* simsrc = g_L + ((size_t)bw*8 + g)*3136;
    for (int idx = tid; idx < 3136; idx += 256) sim_s[idx] = simsrc[idx];
    __syncthreads();

    if (tid >= 224) return;
    const int ti = tid >> 4, tc = tid & 15;
    const int i0 = ti*4, c0 = tc*4;
    const int ch0 = g*64 + c0;

    float asv[4][4], asve[4][4];
    #pragma unroll
    for (int a = 0; a < 4; a++)
        #pragma unroll
        for (int c = 0; c < 4; c++) { asv[a][c]=0.f; asve[a][c]=0.f; }

    #pragma unroll 4
    for (int j = 0; j < 56; j++) {
        const float4 vv = *(const float4*)&Vg[j*64 + c0];
        #pragma unroll
        for (int a = 0; a < 4; a++) {
            const float s = sim_s[(i0+a)*56 + j];
            asv[a][0] = fmaf(s, vv.x, asv[a][0]);
            asv[a][1] = fmaf(s, vv.y, asv[a][1]);
            asv[a][2] = fmaf(s, vv.z, asv[a][2]);
            asv[a][3] = fmaf(s, vv.w, asv[a][3]);
        }
    }
    for (int d = 52 - i0; d <= 110 - i0; d++) {
        const float4 vr = *(const float4*)&vrel_s[d*64 + c0];
        #pragma unroll
        for (int a = 0; a < 4; a++) {
            const int j = i0 + a + d - 55;
            if ((unsigned)j < 56u) {
                const float s = sim_s[(i0+a)*56 + j];
                asve[a][0] = fmaf(s, vr.x, asve[a][0]);
                asve[a][1] = fmaf(s, vr.y, asve[a][1]);
                asve[a][2] = fmaf(s, vr.z, asve[a][2]);
                asve[a][3] = fmaf(s, vr.w, asve[a][3]);
            }
        }
    }

    float s1[4], t1[4], s2[4], t2[4];
    #pragma unroll
    for (int cc = 0; cc < 4; cc++) {
        const int ch = ch0 + cc;
        const float a1 = psv[ch] * rsqrtf(psv[1536+ch] + EPS);
        s1[cc] = a1; t1[cc] = psv[512+ch] - psv[1024+ch]*a1;
        const float a2 = psve[ch] * rsqrtf(psve[1536+ch] + EPS);
        s2[cc] = a2; t2[cc] = psve[512+ch] - psve[1024+ch]*a2;
    }
    #pragma unroll
    for (int a = 0; a < 4; a++) {
        float4 o;
        o.x = asv[a][0]*s1[0] + t1[0] + asve[a][0]*s2[0] + t2[0];
        o.y = asv[a][1]*s1[1] + t1[1] + asve[a][1]*s2[1] + t2[1];
        o.z = asv[a][2]*s1[2] + t1[2] + asve[a][2]*s2[2] + t2[2];
        o.w = asv[a][3]*s1[3] + t1[3] + asve[a][3]*s2[3] + t2[3];
        *(float4*)&out[(((b*56 + i0 + a)*56 + w) * 512) + ch0] = o;
    }
}

// ---------------------------------------------------------------------------
extern "C" void kernel_launch(void* const* d_in, const int* in_sizes, int n_in,
                              void* d_out, int out_size)
{
    const float* x     = (const float*)d_in[0];
    const float* Wq    = (const float*)d_in[1];
    const float* Wk    = (const float*)d_in[2];
    const float* Wv    = (const float*)d_in[3];
    const float* q_rel = (const float*)d_in[4];
    const float* k_rel = (const float*)d_in[5];
    const float* v_rel = (const float*)d_in[6];
    const float* p_q   = (const float*)d_in[7];
    const float* p_k   = (const float*)d_in[8];
    const float* p_v   = (const float*)d_in[9];
    const float* p_qk  = (const float*)d_in[10];
    const float* p_qr  = (const float*)d_in[11];
    const float* p_kr  = (const float*)d_in[12];
    const float* p_sv  = (const float*)d_in[13];
    const float* p_sve = (const float*)d_in[14];
    float* out = (float*)d_out;

    const int smem_k4 = (3584 + 7104 + 3136) * 4;  // 55296 B
    cudaFuncSetAttribute(qkv_mma_kernel,
                         cudaFuncAttributeMaxDynamicSharedMemorySize, SMEM_MMA);
    cudaFuncSetAttribute(logits_mma_kernel,
                         cudaFuncAttributeMaxDynamicSharedMemorySize, SMEM_LOGITS);
    cudaFuncSetAttribute(attn_out_kernel,
                         cudaFuncAttributeMaxDynamicSharedMemorySize, smem_k4);

    split_w_kernel<<<dim3(32, 16), 256>>>(Wq, Wk, Wv);
    qkv_mma_kernel<<<dim3(8, 392), 256, SMEM_MMA>>>(x, p_q, p_k, p_v);
    logits_mma_kernel<<<dim3(896, 8), 128, SMEM_LOGITS>>>(q_rel, k_rel, p_qk, p_qr, p_kr);
    softmax_kernel<<<dim3(49, 8, 16), 64>>>();
    attn_out_kernel<<<dim3(896, 8), 256, smem_k4>>>(v_rel, p_sv, p_sve, out);
}